// round 11
// baseline (speedup 1.0000x reference)
#include <cuda_runtime.h>
#include <cuda_bf16.h>
#include <cuda_fp16.h>
#include <cstdint>

#define B_  2
#define T_  1024
#define S_  1024
#define NQ  16
#define NKV 4
#define HD  128

// Scratch (allocation-free rule: __device__ globals)
__device__ float g_q[B_*T_*NQ*HD];      // (B,T,NQ,HD)
__device__ float g_k[B_*S_*NKV*HD];     // (B,S,NKV,HD)
__device__ float g_v[B_*S_*NKV*HD];
__device__ float g_attn[B_*T_*NQ*HD];

// ---------------------------------------------------------------------------
// helpers
// ---------------------------------------------------------------------------
__device__ __forceinline__ void mma_bf16(float d[4], const uint32_t a[4], const uint32_t b[2]) {
    asm volatile(
        "mma.sync.aligned.m16n8k16.row.col.f32.bf16.bf16.f32 "
        "{%0,%1,%2,%3}, {%4,%5,%6,%7}, {%8,%9}, {%0,%1,%2,%3};\n"
        : "+f"(d[0]), "+f"(d[1]), "+f"(d[2]), "+f"(d[3])
        : "r"(a[0]), "r"(a[1]), "r"(a[2]), "r"(a[3]), "r"(b[0]), "r"(b[1]));
}
__device__ __forceinline__ void mma_fp16(float d[4], const uint32_t a[4], const uint32_t b[2]) {
    asm volatile(
        "mma.sync.aligned.m16n8k16.row.col.f32.f16.f16.f32 "
        "{%0,%1,%2,%3}, {%4,%5,%6,%7}, {%8,%9}, {%0,%1,%2,%3};\n"
        : "+f"(d[0]), "+f"(d[1]), "+f"(d[2]), "+f"(d[3])
        : "r"(a[0]), "r"(a[1]), "r"(a[2]), "r"(a[3]), "r"(b[0]), "r"(b[1]));
}
__device__ __forceinline__ void ldsm_x4(uint32_t r[4], uint32_t addr) {
    asm volatile("ldmatrix.sync.aligned.m8n8.x4.shared.b16 {%0,%1,%2,%3}, [%4];"
                 : "=r"(r[0]), "=r"(r[1]), "=r"(r[2]), "=r"(r[3]) : "r"(addr));
}
__device__ __forceinline__ void ldsm_x4t(uint32_t r[4], uint32_t addr) {
    asm volatile("ldmatrix.sync.aligned.m8n8.x4.trans.shared.b16 {%0,%1,%2,%3}, [%4];"
                 : "=r"(r[0]), "=r"(r[1]), "=r"(r[2]), "=r"(r[3]) : "r"(addr));
}
__device__ __forceinline__ void bf16_split2(float x, float y, uint32_t& hi, uint32_t& lo) {
    __nv_bfloat16 hx = __float2bfloat16(x);
    __nv_bfloat16 hy = __float2bfloat16(y);
    __nv_bfloat16 lx = __float2bfloat16(x - __bfloat162float(hx));
    __nv_bfloat16 ly = __float2bfloat16(y - __bfloat162float(hy));
    hi = (uint32_t)__bfloat16_as_ushort(hx) | ((uint32_t)__bfloat16_as_ushort(hy) << 16);
    lo = (uint32_t)__bfloat16_as_ushort(lx) | ((uint32_t)__bfloat16_as_ushort(ly) << 16);
}
__device__ __forceinline__ uint32_t fp16_pack2(float x, float y) {
    __half2 h = __floats2half2_rn(x, y);
    return *(uint32_t*)&h;
}

// ---------------------------------------------------------------------------
// GEMM core: C[M,N] = A[M,K] @ B[K,N], CTA 128x128, BK=32, 8 warps 2x4.
// PASSES=3: bf16 hi/lo 3-term split. PASSES=1: 1-pass fp16.
// B fragments via ldmatrix.x4.trans (2 n-tiles per LDSM) — R10-confirmed win.
// ---------------------------------------------------------------------------
template<int PASSES>
__device__ __forceinline__ void gemm_core(
    const float* __restrict__ A, const float* __restrict__ Bm, float* __restrict__ C,
    int N, int K, int row0, int col0, char* smraw)
{
    const uint32_t sb = (uint32_t)__cvta_generic_to_shared(smraw);
    constexpr int AHo = 0;
    constexpr int ALo = 10240;
    constexpr int BHo = (PASSES == 3) ? 20480 : 10240;
    constexpr int BLo = 29184;

    const int tid  = threadIdx.x;
    const int lane = tid & 31;
    const int warp = tid >> 5;
    const int grp  = lane >> 2;
    const int qid  = lane & 3;
    const int wm   = (warp >> 2) * 64;
    const int wn   = (warp & 3) * 32;

    float acc[4][4][4];
    #pragma unroll
    for (int i = 0; i < 4; i++)
        #pragma unroll
        for (int j = 0; j < 4; j++)
            #pragma unroll
            for (int c = 0; c < 4; c++) acc[i][j][c] = 0.f;

    float4 aReg[4], bReg[4];
    #pragma unroll
    for (int i = 0; i < 4; i++) {
        int idx = tid + i * 256;
        int ar = idx >> 3, ac = (idx & 7) << 2;
        aReg[i] = *(const float4*)(A + (size_t)(row0 + ar) * K + ac);
        int bk = idx >> 5, bn = (idx & 31) << 2;
        bReg[i] = *(const float4*)(Bm + (size_t)bk * N + col0 + bn);
    }

    for (int k0 = 0; k0 < K; k0 += 32) {
        #pragma unroll
        for (int i = 0; i < 4; i++) {
            int idx = tid + i * 256;
            int ar = idx >> 3, ac = (idx & 7) << 2;
            int aoff = (ar * 40 + ac) << 1;
            int bk = idx >> 5, bn = (idx & 31) << 2;
            int boff = (bk * 136 + bn) << 1;
            if (PASSES == 3) {
                uint32_t h01, l01, h23, l23;
                bf16_split2(aReg[i].x, aReg[i].y, h01, l01);
                bf16_split2(aReg[i].z, aReg[i].w, h23, l23);
                *(uint2*)(smraw + AHo + aoff) = make_uint2(h01, h23);
                *(uint2*)(smraw + ALo + aoff) = make_uint2(l01, l23);
                bf16_split2(bReg[i].x, bReg[i].y, h01, l01);
                bf16_split2(bReg[i].z, bReg[i].w, h23, l23);
                *(uint2*)(smraw + BHo + boff) = make_uint2(h01, h23);
                *(uint2*)(smraw + BLo + boff) = make_uint2(l01, l23);
            } else {
                *(uint2*)(smraw + AHo + aoff) =
                    make_uint2(fp16_pack2(aReg[i].x, aReg[i].y), fp16_pack2(aReg[i].z, aReg[i].w));
                *(uint2*)(smraw + BHo + boff) =
                    make_uint2(fp16_pack2(bReg[i].x, bReg[i].y), fp16_pack2(bReg[i].z, bReg[i].w));
            }
        }
        __syncthreads();

        if (k0 + 32 < K) {
            #pragma unroll
            for (int i = 0; i < 4; i++) {
                int idx = tid + i * 256;
                int ar = idx >> 3, ac = (idx & 7) << 2;
                aReg[i] = *(const float4*)(A + (size_t)(row0 + ar) * K + k0 + 32 + ac);
                int bk = idx >> 5, bn = (idx & 31) << 2;
                bReg[i] = *(const float4*)(Bm + (size_t)(k0 + 32 + bk) * N + col0 + bn);
            }
        }

        #pragma unroll
        for (int kk = 0; kk < 32; kk += 16) {
            uint32_t ah[4][4], al[4][4];
            #pragma unroll
            for (int im = 0; im < 4; im++) {
                int m = wm + im * 16 + (lane & 15);
                uint32_t ab = sb + AHo + ((m * 40 + kk + ((lane >> 4) << 3)) << 1);
                ldsm_x4(ah[im], ab);
                if (PASSES == 3) ldsm_x4(al[im], ab + (ALo - AHo));
            }
            uint32_t bh[4][2], bl[4][2];
            #pragma unroll
            for (int pr = 0; pr < 2; pr++) {
                int kr = kk + (lane & 15);
                uint32_t bb = sb + BHo + ((kr * 136 + wn + pr * 16 + ((lane >> 4) << 3)) << 1);
                uint32_t t4[4];
                ldsm_x4t(t4, bb);
                bh[2*pr][0] = t4[0]; bh[2*pr][1] = t4[1];
                bh[2*pr+1][0] = t4[2]; bh[2*pr+1][1] = t4[3];
                if (PASSES == 3) {
                    ldsm_x4t(t4, bb + (BLo - BHo));
                    bl[2*pr][0] = t4[0]; bl[2*pr][1] = t4[1];
                    bl[2*pr+1][0] = t4[2]; bl[2*pr+1][1] = t4[3];
                }
            }
            #pragma unroll
            for (int im = 0; im < 4; im++)
                #pragma unroll
                for (int in_ = 0; in_ < 4; in_++) {
                    if (PASSES == 3) {
                        mma_bf16(acc[im][in_], ah[im], bh[in_]);
                        mma_bf16(acc[im][in_], ah[im], bl[in_]);
                        mma_bf16(acc[im][in_], al[im], bh[in_]);
                    } else {
                        mma_fp16(acc[im][in_], ah[im], bh[in_]);
                    }
                }
        }
        __syncthreads();
    }

    #pragma unroll
    for (int im = 0; im < 4; im++) {
        int r = row0 + wm + im * 16 + grp;
        #pragma unroll
        for (int in_ = 0; in_ < 4; in_++) {
            int nc = col0 + wn + in_ * 8 + 2 * qid;
            *(float2*)(C + (size_t)r * N + nc)       = make_float2(acc[im][in_][0], acc[im][in_][1]);
            *(float2*)(C + (size_t)(r + 8) * N + nc) = make_float2(acc[im][in_][2], acc[im][in_][3]);
        }
    }
}

// Merged Q/K/V projections, occ-2.
__global__ void __launch_bounds__(256, 2) proj_qkv(
    const float* __restrict__ Xq, const float* __restrict__ Wq, float* __restrict__ Cq,
    const float* __restrict__ Xkv, const float* __restrict__ Wk, float* __restrict__ Ck,
    const float* __restrict__ Wv, float* __restrict__ Cv)
{
    extern __shared__ char smraw[];
    const int bx = blockIdx.x;
    const int row0 = blockIdx.y * 128;
    if (bx < 16)
        gemm_core<3>(Xq, Wq, Cq, 2048, 2048, row0, bx * 128, smraw);
    else if (bx < 20)
        gemm_core<3>(Xkv, Wk, Ck, 512, 2048, row0, (bx - 16) * 128, smraw);
    else
        gemm_core<1>(Xkv, Wv, Cv, 512, 2048, row0, (bx - 20) * 128, smraw);
}

// Output projection (fp16 1-pass), occ-2.
__global__ void __launch_bounds__(256, 2) gemm_o(
    const float* __restrict__ A, const float* __restrict__ Bm, float* __restrict__ C)
{
    extern __shared__ char smraw[];
    gemm_core<1>(A, Bm, C, 2048, 2048, blockIdx.y * 128, blockIdx.x * 128, smraw);
}

// ---------------- RoPE fused (q then k ranges in one grid) ----------------
#define QROPE_TOTAL (B_*T_*NQ*64)
#define KROPE_TOTAL (B_*S_*NKV*64)

__global__ void rope_fused(float* __restrict__ xq, float* __restrict__ xk,
                           const int* __restrict__ qpos, const int* __restrict__ kpos)
{
    int idx = blockIdx.x * blockDim.x + threadIdx.x;
    float* x;
    const int* pos;
    int Nh;
    if (idx < QROPE_TOTAL) {
        x = xq; pos = qpos; Nh = NQ;
    } else {
        idx -= QROPE_TOTAL;
        if (idx >= KROPE_TOTAL) return;
        x = xk; pos = kpos; Nh = NKV;
    }
    int i   = idx & 63;
    int bln = idx >> 6;
    int bl  = bln / Nh;
    float p    = (float)pos[bl];
    float frac = (float)i * (1.0f / 64.0f);
    float ts   = powf(10000.0f, frac);
    float ang  = p / ts;
    float si = sinf(ang), co = cosf(ang);
    float* base = x + (size_t)bln * HD;
    float x1 = base[i], x2 = base[i + 64];
    base[i]      = x1 * co - x2 * si;
    base[i + 64] = x2 * co + x1 * si;
}

// ---------------------------------------------------------------------------
// Flash attention (R9-verified): occ-2, KV block 32 single-buffered, bf16-3x
// QK^T, fp16 PV with register-built A fragments. Padded smem strides.
// Smem: QH 0 (34816), QL 34816, KH 69632 (8704), KL 78336, VS 87040 (8704).
// Total 95744 -> 2 CTAs/SM.
// ---------------------------------------------------------------------------
#define A_QH 0
#define A_QL 34816
#define A_KH 69632
#define A_KL 78336
#define A_VS 87040
#define A_SMEM 95744
#define VSH 136

__global__ void __launch_bounds__(256, 2) attn_tc_kernel(
    const float* __restrict__ q, const float* __restrict__ k,
    const float* __restrict__ v, float* __restrict__ o)
{
    extern __shared__ char smraw[];
    const uint32_t sb = (uint32_t)__cvta_generic_to_shared(smraw);

    const int tid  = threadIdx.x;
    const int lane = tid & 31;
    const int warp = tid >> 5;
    const int grp  = lane >> 2;
    const int qid  = lane & 3;
    const int wm   = warp * 16;
    const int t0   = blockIdx.x * 128;
    const int n    = blockIdx.y;
    const int b    = blockIdx.z;
    const int kvh  = n >> 2;

    const float* Qg = q + ((size_t)(b * T_ + t0) * NQ  + n)   * HD;
    const float* Kg = k + ((size_t)(b * S_)      * NKV + kvh) * HD;
    const float* Vg = v + ((size_t)(b * S_)      * NKV + kvh) * HD;

    for (int f = tid; f < 128 * 32; f += 256) {
        int r = f >> 5, c4 = (f & 31) << 2;
        float4 a = *(const float4*)(Qg + (size_t)r * (NQ * HD) + c4);
        uint32_t h01, l01, h23, l23;
        bf16_split2(a.x, a.y, h01, l01);
        bf16_split2(a.z, a.w, h23, l23);
        int off = (r * 136 + c4) << 1;
        *(uint2*)(smraw + A_QH + off) = make_uint2(h01, h23);
        *(uint2*)(smraw + A_QL + off) = make_uint2(l01, l23);
    }

    float m0 = -1e30f, m1 = -1e30f, l0 = 0.f, l1 = 0.f;
    float oacc[16][4];
    #pragma unroll
    for (int j = 0; j < 16; j++)
        #pragma unroll
        for (int c = 0; c < 4; c++) oacc[j][c] = 0.f;

    for (int blk = 0; blk < 32; blk++) {
        __syncthreads();
        {
            const int s0 = blk * 32;
            #pragma unroll
            for (int i = 0; i < 4; i++) {
                int f = tid + i * 256;
                int r = f >> 5, c4 = (f & 31) << 2;
                float4 a = *(const float4*)(Kg + (size_t)(s0 + r) * (NKV * HD) + c4);
                uint32_t h01, l01, h23, l23;
                bf16_split2(a.x, a.y, h01, l01);
                bf16_split2(a.z, a.w, h23, l23);
                int off = (r * 136 + c4) << 1;
                *(uint2*)(smraw + A_KH + off) = make_uint2(h01, h23);
                *(uint2*)(smraw + A_KL + off) = make_uint2(l01, l23);
                float4 vv = *(const float4*)(Vg + (size_t)(s0 + r) * (NKV * HD) + c4);
                *(uint2*)(smraw + A_VS + ((r * VSH + c4) << 1)) =
                    make_uint2(fp16_pack2(vv.x, vv.y), fp16_pack2(vv.z, vv.w));
            }
        }
        __syncthreads();

        float sacc[4][4];
        #pragma unroll
        for (int j = 0; j < 4; j++)
            #pragma unroll
            for (int c = 0; c < 4; c++) sacc[j][c] = 0.f;

        #pragma unroll
        for (int kk = 0; kk < 8; kk++) {
            const int col0h = kk * 16;
            uint32_t ah[4], al[4];
            {
                int m = wm + (lane & 15);
                uint32_t ab = sb + A_QH + ((m * 136 + col0h + ((lane >> 4) << 3)) << 1);
                ldsm_x4(ah, ab);
                ldsm_x4(al, ab + (A_QL - A_QH));
            }
            #pragma unroll
            for (int j2 = 0; j2 < 2; j2++) {
                int row = (j2 * 2 + (lane >> 4)) * 8 + (lane & 7);
                uint32_t bb = sb + A_KH + ((row * 136 + col0h + (lane & 8)) << 1);
                uint32_t bh4[4], bl4[4];
                ldsm_x4(bh4, bb);
                ldsm_x4(bl4, bb + (A_KL - A_KH));
                mma_bf16(sacc[2*j2],   ah, bh4);
                mma_bf16(sacc[2*j2],   ah, bl4);
                mma_bf16(sacc[2*j2],   al, bh4);
                mma_bf16(sacc[2*j2+1], ah, bh4 + 2);
                mma_bf16(sacc[2*j2+1], ah, bl4 + 2);
                mma_bf16(sacc[2*j2+1], al, bh4 + 2);
            }
        }

        float mx0 = -1e30f, mx1 = -1e30f;
        #pragma unroll
        for (int j = 0; j < 4; j++) {
            mx0 = fmaxf(mx0, fmaxf(sacc[j][0], sacc[j][1]));
            mx1 = fmaxf(mx1, fmaxf(sacc[j][2], sacc[j][3]));
        }
        #pragma unroll
        for (int off = 1; off < 4; off <<= 1) {
            mx0 = fmaxf(mx0, __shfl_xor_sync(0xffffffffu, mx0, off));
            mx1 = fmaxf(mx1, __shfl_xor_sync(0xffffffffu, mx1, off));
        }
        float mn0 = fmaxf(m0, mx0), mn1 = fmaxf(m1, mx1);
        float cr0 = __expf(m0 - mn0), cr1 = __expf(m1 - mn1);
        float ps0 = 0.f, ps1 = 0.f;
        uint32_t pk[4][2];
        #pragma unroll
        for (int j = 0; j < 4; j++) {
            float e0 = __expf(sacc[j][0] - mn0);
            float e1 = __expf(sacc[j][1] - mn0);
            float e2 = __expf(sacc[j][2] - mn1);
            float e3 = __expf(sacc[j][3] - mn1);
            ps0 += e0 + e1; ps1 += e2 + e3;
            pk[j][0] = fp16_pack2(e0, e1);
            pk[j][1] = fp16_pack2(e2, e3);
        }
        #pragma unroll
        for (int off = 1; off < 4; off <<= 1) {
            ps0 += __shfl_xor_sync(0xffffffffu, ps0, off);
            ps1 += __shfl_xor_sync(0xffffffffu, ps1, off);
        }
        l0 = l0 * cr0 + ps0; m0 = mn0;
        l1 = l1 * cr1 + ps1; m1 = mn1;
        #pragma unroll
        for (int j = 0; j < 16; j++) {
            oacc[j][0] *= cr0; oacc[j][1] *= cr0;
            oacc[j][2] *= cr1; oacc[j][3] *= cr1;
        }

        #pragma unroll
        for (int kk2 = 0; kk2 < 2; kk2++) {
            uint32_t pa[4] = { pk[2*kk2][0], pk[2*kk2][1], pk[2*kk2+1][0], pk[2*kk2+1][1] };
            #pragma unroll
            for (int j2 = 0; j2 < 8; j2++) {
                int kr  = kk2 * 16 + (lane & 15);
                int col = (j2 * 2 + (lane >> 4)) * 8;
                uint32_t vb4[4];
                ldsm_x4t(vb4, sb + A_VS + ((kr * VSH + col) << 1));
                mma_fp16(oacc[2*j2],     pa, vb4);
                mma_fp16(oacc[2*j2 + 1], pa, vb4 + 2);
            }
        }
    }

    float inv0 = 1.0f / l0, inv1 = 1.0f / l1;
    float* o0 = o + ((size_t)(b * T_ + t0 + wm + grp)     * NQ + n) * HD;
    float* o1 = o + ((size_t)(b * T_ + t0 + wm + grp + 8) * NQ + n) * HD;
    #pragma unroll
    for (int j = 0; j < 16; j++) {
        int col = j * 8 + 2 * qid;
        *(float2*)(o0 + col) = make_float2(oacc[j][0] * inv0, oacc[j][1] * inv0);
        *(float2*)(o1 + col) = make_float2(oacc[j][2] * inv1, oacc[j][3] * inv1);
    }
}

// ---------------- Launch ----------------
extern "C" void kernel_launch(void* const* d_in, const int* in_sizes, int n_in,
                              void* d_out, int out_size)
{
    const float* Xq  = (const float*)d_in[0];
    const float* Xkv = (const float*)d_in[1];
    const int*   qpos = (const int*)d_in[2];
    const int*   kpos = (const int*)d_in[3];
    const float* Wq  = (const float*)d_in[4];
    const float* Wk  = (const float*)d_in[5];
    const float* Wv  = (const float*)d_in[6];
    const float* Wo  = (const float*)d_in[7];
    float* out = (float*)d_out;

    float *qb, *kb, *vb, *ab;
    cudaGetSymbolAddress((void**)&qb, g_q);
    cudaGetSymbolAddress((void**)&kb, g_k);
    cudaGetSymbolAddress((void**)&vb, g_v);
    cudaGetSymbolAddress((void**)&ab, g_attn);

    const int P_SMEM = 37888;
    const int O_SMEM = 18944;
    cudaFuncSetAttribute(proj_qkv, cudaFuncAttributeMaxDynamicSharedMemorySize, P_SMEM);
    cudaFuncSetAttribute(gemm_o, cudaFuncAttributeMaxDynamicSharedMemorySize, O_SMEM);
    cudaFuncSetAttribute(attn_tc_kernel, cudaFuncAttributeMaxDynamicSharedMemorySize, A_SMEM);

    // Q/K/V projections in one launch (occ-2, x4t B fragments)
    proj_qkv<<<dim3(24, 16), 256, P_SMEM>>>(Xq, Wq, qb, Xkv, Wk, kb, Wv, vb);

    // RoPE on q and k, one launch
    rope_fused<<<(QROPE_TOTAL + KROPE_TOTAL + 255) / 256, 256>>>(qb, kb, qpos, kpos);

    // Attention (R9 config: occ-2, padded smem, register-P PV)
    attn_tc_kernel<<<dim3(T_/128, NQ, B_), 256, A_SMEM>>>(qb, kb, vb, ab);

    // Output projection (occ-2, x4t B fragments)
    gemm_o<<<dim3(16, 16), 256, O_SMEM>>>(ab, Wo, out);
}

// round 12
// speedup vs baseline: 1.0327x; 1.0327x over previous
#include <cuda_runtime.h>
#include <cuda_bf16.h>
#include <cuda_fp16.h>
#include <cstdint>

#define B_  2
#define T_  1024
#define S_  1024
#define NQ  16
#define NKV 4
#define HD  128

// Scratch (allocation-free rule: __device__ globals)
__device__ float g_q[B_*T_*NQ*HD];      // (B,T,NQ,HD)
__device__ float g_k[B_*S_*NKV*HD];     // (B,S,NKV,HD)
__device__ float g_v[B_*S_*NKV*HD];
__device__ float g_attn[B_*T_*NQ*HD];

// ---------------------------------------------------------------------------
// helpers
// ---------------------------------------------------------------------------
__device__ __forceinline__ void mma_bf16(float d[4], const uint32_t a[4], const uint32_t b[2]) {
    asm volatile(
        "mma.sync.aligned.m16n8k16.row.col.f32.bf16.bf16.f32 "
        "{%0,%1,%2,%3}, {%4,%5,%6,%7}, {%8,%9}, {%0,%1,%2,%3};\n"
        : "+f"(d[0]), "+f"(d[1]), "+f"(d[2]), "+f"(d[3])
        : "r"(a[0]), "r"(a[1]), "r"(a[2]), "r"(a[3]), "r"(b[0]), "r"(b[1]));
}
__device__ __forceinline__ void mma_fp16(float d[4], const uint32_t a[4], const uint32_t b[2]) {
    asm volatile(
        "mma.sync.aligned.m16n8k16.row.col.f32.f16.f16.f32 "
        "{%0,%1,%2,%3}, {%4,%5,%6,%7}, {%8,%9}, {%0,%1,%2,%3};\n"
        : "+f"(d[0]), "+f"(d[1]), "+f"(d[2]), "+f"(d[3])
        : "r"(a[0]), "r"(a[1]), "r"(a[2]), "r"(a[3]), "r"(b[0]), "r"(b[1]));
}
__device__ __forceinline__ void ldsm_x4(uint32_t r[4], uint32_t addr) {
    asm volatile("ldmatrix.sync.aligned.m8n8.x4.shared.b16 {%0,%1,%2,%3}, [%4];"
                 : "=r"(r[0]), "=r"(r[1]), "=r"(r[2]), "=r"(r[3]) : "r"(addr));
}
__device__ __forceinline__ void ldsm_x4t(uint32_t r[4], uint32_t addr) {
    asm volatile("ldmatrix.sync.aligned.m8n8.x4.trans.shared.b16 {%0,%1,%2,%3}, [%4];"
                 : "=r"(r[0]), "=r"(r[1]), "=r"(r[2]), "=r"(r[3]) : "r"(addr));
}
__device__ __forceinline__ void ldsm_x2t(uint32_t r[2], uint32_t addr) {
    asm volatile("ldmatrix.sync.aligned.m8n8.x2.trans.shared.b16 {%0,%1}, [%2];"
                 : "=r"(r[0]), "=r"(r[1]) : "r"(addr));
}
__device__ __forceinline__ void bf16_split2(float x, float y, uint32_t& hi, uint32_t& lo) {
    __nv_bfloat16 hx = __float2bfloat16(x);
    __nv_bfloat16 hy = __float2bfloat16(y);
    __nv_bfloat16 lx = __float2bfloat16(x - __bfloat162float(hx));
    __nv_bfloat16 ly = __float2bfloat16(y - __bfloat162float(hy));
    hi = (uint32_t)__bfloat16_as_ushort(hx) | ((uint32_t)__bfloat16_as_ushort(hy) << 16);
    lo = (uint32_t)__bfloat16_as_ushort(lx) | ((uint32_t)__bfloat16_as_ushort(ly) << 16);
}
__device__ __forceinline__ uint32_t fp16_pack2(float x, float y) {
    __half2 h = __floats2half2_rn(x, y);
    return *(uint32_t*)&h;
}

// ---------------------------------------------------------------------------
// GEMM core: C[M,N] = A[M,K] @ B[K,N], CTA 128x128, BK=32, 8 warps 2x4.
// PASSES=3: bf16 hi/lo 3-term split (X4T=0: x2t B gather — reg-pressure-safe).
// PASSES=1: 1-pass fp16 (X4T=1: x4t B gather — confirmed win, regs slack).
// ---------------------------------------------------------------------------
template<int PASSES, int X4T>
__device__ __forceinline__ void gemm_core(
    const float* __restrict__ A, const float* __restrict__ Bm, float* __restrict__ C,
    int N, int K, int row0, int col0, char* smraw)
{
    const uint32_t sb = (uint32_t)__cvta_generic_to_shared(smraw);
    constexpr int AHo = 0;
    constexpr int ALo = 10240;
    constexpr int BHo = (PASSES == 3) ? 20480 : 10240;
    constexpr int BLo = 29184;

    const int tid  = threadIdx.x;
    const int lane = tid & 31;
    const int warp = tid >> 5;
    const int grp  = lane >> 2;
    const int qid  = lane & 3;
    const int wm   = (warp >> 2) * 64;
    const int wn   = (warp & 3) * 32;

    float acc[4][4][4];
    #pragma unroll
    for (int i = 0; i < 4; i++)
        #pragma unroll
        for (int j = 0; j < 4; j++)
            #pragma unroll
            for (int c = 0; c < 4; c++) acc[i][j][c] = 0.f;

    float4 aReg[4], bReg[4];
    #pragma unroll
    for (int i = 0; i < 4; i++) {
        int idx = tid + i * 256;
        int ar = idx >> 3, ac = (idx & 7) << 2;
        aReg[i] = *(const float4*)(A + (size_t)(row0 + ar) * K + ac);
        int bk = idx >> 5, bn = (idx & 31) << 2;
        bReg[i] = *(const float4*)(Bm + (size_t)bk * N + col0 + bn);
    }

    for (int k0 = 0; k0 < K; k0 += 32) {
        #pragma unroll
        for (int i = 0; i < 4; i++) {
            int idx = tid + i * 256;
            int ar = idx >> 3, ac = (idx & 7) << 2;
            int aoff = (ar * 40 + ac) << 1;
            int bk = idx >> 5, bn = (idx & 31) << 2;
            int boff = (bk * 136 + bn) << 1;
            if (PASSES == 3) {
                uint32_t h01, l01, h23, l23;
                bf16_split2(aReg[i].x, aReg[i].y, h01, l01);
                bf16_split2(aReg[i].z, aReg[i].w, h23, l23);
                *(uint2*)(smraw + AHo + aoff) = make_uint2(h01, h23);
                *(uint2*)(smraw + ALo + aoff) = make_uint2(l01, l23);
                bf16_split2(bReg[i].x, bReg[i].y, h01, l01);
                bf16_split2(bReg[i].z, bReg[i].w, h23, l23);
                *(uint2*)(smraw + BHo + boff) = make_uint2(h01, h23);
                *(uint2*)(smraw + BLo + boff) = make_uint2(l01, l23);
            } else {
                *(uint2*)(smraw + AHo + aoff) =
                    make_uint2(fp16_pack2(aReg[i].x, aReg[i].y), fp16_pack2(aReg[i].z, aReg[i].w));
                *(uint2*)(smraw + BHo + boff) =
                    make_uint2(fp16_pack2(bReg[i].x, bReg[i].y), fp16_pack2(bReg[i].z, bReg[i].w));
            }
        }
        __syncthreads();

        if (k0 + 32 < K) {
            #pragma unroll
            for (int i = 0; i < 4; i++) {
                int idx = tid + i * 256;
                int ar = idx >> 3, ac = (idx & 7) << 2;
                aReg[i] = *(const float4*)(A + (size_t)(row0 + ar) * K + k0 + 32 + ac);
                int bk = idx >> 5, bn = (idx & 31) << 2;
                bReg[i] = *(const float4*)(Bm + (size_t)(k0 + 32 + bk) * N + col0 + bn);
            }
        }

        #pragma unroll
        for (int kk = 0; kk < 32; kk += 16) {
            uint32_t ah[4][4], al[4][4];
            #pragma unroll
            for (int im = 0; im < 4; im++) {
                int m = wm + im * 16 + (lane & 15);
                uint32_t ab = sb + AHo + ((m * 40 + kk + ((lane >> 4) << 3)) << 1);
                ldsm_x4(ah[im], ab);
                if (PASSES == 3) ldsm_x4(al[im], ab + (ALo - AHo));
            }
            uint32_t bh[4][2], bl[4][2];
            if (X4T) {
                #pragma unroll
                for (int pr = 0; pr < 2; pr++) {
                    int kr = kk + (lane & 15);
                    uint32_t bb = sb + BHo + ((kr * 136 + wn + pr * 16 + ((lane >> 4) << 3)) << 1);
                    uint32_t t4[4];
                    ldsm_x4t(t4, bb);
                    bh[2*pr][0] = t4[0]; bh[2*pr][1] = t4[1];
                    bh[2*pr+1][0] = t4[2]; bh[2*pr+1][1] = t4[3];
                    if (PASSES == 3) {
                        ldsm_x4t(t4, bb + (BLo - BHo));
                        bl[2*pr][0] = t4[0]; bl[2*pr][1] = t4[1];
                        bl[2*pr+1][0] = t4[2]; bl[2*pr+1][1] = t4[3];
                    }
                }
            } else {
                #pragma unroll
                for (int in_ = 0; in_ < 4; in_++) {
                    int kr = kk + (lane & 15);
                    uint32_t bb = sb + BHo + ((kr * 136 + wn + in_ * 8) << 1);
                    ldsm_x2t(bh[in_], bb);
                    if (PASSES == 3) ldsm_x2t(bl[in_], bb + (BLo - BHo));
                }
            }
            #pragma unroll
            for (int im = 0; im < 4; im++)
                #pragma unroll
                for (int in_ = 0; in_ < 4; in_++) {
                    if (PASSES == 3) {
                        mma_bf16(acc[im][in_], ah[im], bh[in_]);
                        mma_bf16(acc[im][in_], ah[im], bl[in_]);
                        mma_bf16(acc[im][in_], al[im], bh[in_]);
                    } else {
                        mma_fp16(acc[im][in_], ah[im], bh[in_]);
                    }
                }
        }
        __syncthreads();
    }

    #pragma unroll
    for (int im = 0; im < 4; im++) {
        int r = row0 + wm + im * 16 + grp;
        #pragma unroll
        for (int in_ = 0; in_ < 4; in_++) {
            int nc = col0 + wn + in_ * 8 + 2 * qid;
            *(float2*)(C + (size_t)r * N + nc)       = make_float2(acc[im][in_][0], acc[im][in_][1]);
            *(float2*)(C + (size_t)(r + 8) * N + nc) = make_float2(acc[im][in_][2], acc[im][in_][3]);
        }
    }
}

// Merged Q/K/V projections, occ-2. bf3 paths: x2t (R9); fp16 path: x4t (R10 win).
__global__ void __launch_bounds__(256, 2) proj_qkv(
    const float* __restrict__ Xq, const float* __restrict__ Wq, float* __restrict__ Cq,
    const float* __restrict__ Xkv, const float* __restrict__ Wk, float* __restrict__ Ck,
    const float* __restrict__ Wv, float* __restrict__ Cv)
{
    extern __shared__ char smraw[];
    const int bx = blockIdx.x;
    const int row0 = blockIdx.y * 128;
    if (bx < 16)
        gemm_core<3, 0>(Xq, Wq, Cq, 2048, 2048, row0, bx * 128, smraw);
    else if (bx < 20)
        gemm_core<3, 0>(Xkv, Wk, Ck, 512, 2048, row0, (bx - 16) * 128, smraw);
    else
        gemm_core<1, 1>(Xkv, Wv, Cv, 512, 2048, row0, (bx - 20) * 128, smraw);
}

// Output projection (fp16 1-pass, x4t), occ-2.
__global__ void __launch_bounds__(256, 2) gemm_o(
    const float* __restrict__ A, const float* __restrict__ Bm, float* __restrict__ C)
{
    extern __shared__ char smraw[];
    gemm_core<1, 1>(A, Bm, C, 2048, 2048, blockIdx.y * 128, blockIdx.x * 128, smraw);
}

// ---------------- RoPE fused (q then k ranges in one grid) ----------------
#define QROPE_TOTAL (B_*T_*NQ*64)
#define KROPE_TOTAL (B_*S_*NKV*64)

__global__ void rope_fused(float* __restrict__ xq, float* __restrict__ xk,
                           const int* __restrict__ qpos, const int* __restrict__ kpos)
{
    int idx = blockIdx.x * blockDim.x + threadIdx.x;
    float* x;
    const int* pos;
    int Nh;
    if (idx < QROPE_TOTAL) {
        x = xq; pos = qpos; Nh = NQ;
    } else {
        idx -= QROPE_TOTAL;
        if (idx >= KROPE_TOTAL) return;
        x = xk; pos = kpos; Nh = NKV;
    }
    int i   = idx & 63;
    int bln = idx >> 6;
    int bl  = bln / Nh;
    float p    = (float)pos[bl];
    float frac = (float)i * (1.0f / 64.0f);
    float ts   = powf(10000.0f, frac);
    float ang  = p / ts;
    float si = sinf(ang), co = cosf(ang);
    float* base = x + (size_t)bln * HD;
    float x1 = base[i], x2 = base[i + 64];
    base[i]      = x1 * co - x2 * si;
    base[i + 64] = x2 * co + x1 * si;
}

// ---------------------------------------------------------------------------
// Flash attention (R9-verified, byte-identical): occ-2, KV block 32,
// bf16-3x QK^T, fp16 PV with register-built A fragments.
// Smem: QH 0 (34816), QL 34816, KH 69632 (8704), KL 78336, VS 87040 (8704).
// Total 95744 -> 2 CTAs/SM.
// ---------------------------------------------------------------------------
#define A_QH 0
#define A_QL 34816
#define A_KH 69632
#define A_KL 78336
#define A_VS 87040
#define A_SMEM 95744
#define VSH 136

__global__ void __launch_bounds__(256, 2) attn_tc_kernel(
    const float* __restrict__ q, const float* __restrict__ k,
    const float* __restrict__ v, float* __restrict__ o)
{
    extern __shared__ char smraw[];
    const uint32_t sb = (uint32_t)__cvta_generic_to_shared(smraw);

    const int tid  = threadIdx.x;
    const int lane = tid & 31;
    const int warp = tid >> 5;
    const int grp  = lane >> 2;
    const int qid  = lane & 3;
    const int wm   = warp * 16;
    const int t0   = blockIdx.x * 128;
    const int n    = blockIdx.y;
    const int b    = blockIdx.z;
    const int kvh  = n >> 2;

    const float* Qg = q + ((size_t)(b * T_ + t0) * NQ  + n)   * HD;
    const float* Kg = k + ((size_t)(b * S_)      * NKV + kvh) * HD;
    const float* Vg = v + ((size_t)(b * S_)      * NKV + kvh) * HD;

    for (int f = tid; f < 128 * 32; f += 256) {
        int r = f >> 5, c4 = (f & 31) << 2;
        float4 a = *(const float4*)(Qg + (size_t)r * (NQ * HD) + c4);
        uint32_t h01, l01, h23, l23;
        bf16_split2(a.x, a.y, h01, l01);
        bf16_split2(a.z, a.w, h23, l23);
        int off = (r * 136 + c4) << 1;
        *(uint2*)(smraw + A_QH + off) = make_uint2(h01, h23);
        *(uint2*)(smraw + A_QL + off) = make_uint2(l01, l23);
    }

    float m0 = -1e30f, m1 = -1e30f, l0 = 0.f, l1 = 0.f;
    float oacc[16][4];
    #pragma unroll
    for (int j = 0; j < 16; j++)
        #pragma unroll
        for (int c = 0; c < 4; c++) oacc[j][c] = 0.f;

    for (int blk = 0; blk < 32; blk++) {
        __syncthreads();
        {
            const int s0 = blk * 32;
            #pragma unroll
            for (int i = 0; i < 4; i++) {
                int f = tid + i * 256;
                int r = f >> 5, c4 = (f & 31) << 2;
                float4 a = *(const float4*)(Kg + (size_t)(s0 + r) * (NKV * HD) + c4);
                uint32_t h01, l01, h23, l23;
                bf16_split2(a.x, a.y, h01, l01);
                bf16_split2(a.z, a.w, h23, l23);
                int off = (r * 136 + c4) << 1;
                *(uint2*)(smraw + A_KH + off) = make_uint2(h01, h23);
                *(uint2*)(smraw + A_KL + off) = make_uint2(l01, l23);
                float4 vv = *(const float4*)(Vg + (size_t)(s0 + r) * (NKV * HD) + c4);
                *(uint2*)(smraw + A_VS + ((r * VSH + c4) << 1)) =
                    make_uint2(fp16_pack2(vv.x, vv.y), fp16_pack2(vv.z, vv.w));
            }
        }
        __syncthreads();

        float sacc[4][4];
        #pragma unroll
        for (int j = 0; j < 4; j++)
            #pragma unroll
            for (int c = 0; c < 4; c++) sacc[j][c] = 0.f;

        #pragma unroll
        for (int kk = 0; kk < 8; kk++) {
            const int col0h = kk * 16;
            uint32_t ah[4], al[4];
            {
                int m = wm + (lane & 15);
                uint32_t ab = sb + A_QH + ((m * 136 + col0h + ((lane >> 4) << 3)) << 1);
                ldsm_x4(ah, ab);
                ldsm_x4(al, ab + (A_QL - A_QH));
            }
            #pragma unroll
            for (int j2 = 0; j2 < 2; j2++) {
                int row = (j2 * 2 + (lane >> 4)) * 8 + (lane & 7);
                uint32_t bb = sb + A_KH + ((row * 136 + col0h + (lane & 8)) << 1);
                uint32_t bh4[4], bl4[4];
                ldsm_x4(bh4, bb);
                ldsm_x4(bl4, bb + (A_KL - A_KH));
                mma_bf16(sacc[2*j2],   ah, bh4);
                mma_bf16(sacc[2*j2],   ah, bl4);
                mma_bf16(sacc[2*j2],   al, bh4);
                mma_bf16(sacc[2*j2+1], ah, bh4 + 2);
                mma_bf16(sacc[2*j2+1], ah, bl4 + 2);
                mma_bf16(sacc[2*j2+1], al, bh4 + 2);
            }
        }

        float mx0 = -1e30f, mx1 = -1e30f;
        #pragma unroll
        for (int j = 0; j < 4; j++) {
            mx0 = fmaxf(mx0, fmaxf(sacc[j][0], sacc[j][1]));
            mx1 = fmaxf(mx1, fmaxf(sacc[j][2], sacc[j][3]));
        }
        #pragma unroll
        for (int off = 1; off < 4; off <<= 1) {
            mx0 = fmaxf(mx0, __shfl_xor_sync(0xffffffffu, mx0, off));
            mx1 = fmaxf(mx1, __shfl_xor_sync(0xffffffffu, mx1, off));
        }
        float mn0 = fmaxf(m0, mx0), mn1 = fmaxf(m1, mx1);
        float cr0 = __expf(m0 - mn0), cr1 = __expf(m1 - mn1);
        float ps0 = 0.f, ps1 = 0.f;
        uint32_t pk[4][2];
        #pragma unroll
        for (int j = 0; j < 4; j++) {
            float e0 = __expf(sacc[j][0] - mn0);
            float e1 = __expf(sacc[j][1] - mn0);
            float e2 = __expf(sacc[j][2] - mn1);
            float e3 = __expf(sacc[j][3] - mn1);
            ps0 += e0 + e1; ps1 += e2 + e3;
            pk[j][0] = fp16_pack2(e0, e1);
            pk[j][1] = fp16_pack2(e2, e3);
        }
        #pragma unroll
        for (int off = 1; off < 4; off <<= 1) {
            ps0 += __shfl_xor_sync(0xffffffffu, ps0, off);
            ps1 += __shfl_xor_sync(0xffffffffu, ps1, off);
        }
        l0 = l0 * cr0 + ps0; m0 = mn0;
        l1 = l1 * cr1 + ps1; m1 = mn1;
        #pragma unroll
        for (int j = 0; j < 16; j++) {
            oacc[j][0] *= cr0; oacc[j][1] *= cr0;
            oacc[j][2] *= cr1; oacc[j][3] *= cr1;
        }

        #pragma unroll
        for (int kk2 = 0; kk2 < 2; kk2++) {
            uint32_t pa[4] = { pk[2*kk2][0], pk[2*kk2][1], pk[2*kk2+1][0], pk[2*kk2+1][1] };
            #pragma unroll
            for (int j2 = 0; j2 < 8; j2++) {
                int kr  = kk2 * 16 + (lane & 15);
                int col = (j2 * 2 + (lane >> 4)) * 8;
                uint32_t vb4[4];
                ldsm_x4t(vb4, sb + A_VS + ((kr * VSH + col) << 1));
                mma_fp16(oacc[2*j2],     pa, vb4);
                mma_fp16(oacc[2*j2 + 1], pa, vb4 + 2);
            }
        }
    }

    float inv0 = 1.0f / l0, inv1 = 1.0f / l1;
    float* o0 = o + ((size_t)(b * T_ + t0 + wm + grp)     * NQ + n) * HD;
    float* o1 = o + ((size_t)(b * T_ + t0 + wm + grp + 8) * NQ + n) * HD;
    #pragma unroll
    for (int j = 0; j < 16; j++) {
        int col = j * 8 + 2 * qid;
        *(float2*)(o0 + col) = make_float2(oacc[j][0] * inv0, oacc[j][1] * inv0);
        *(float2*)(o1 + col) = make_float2(oacc[j][2] * inv1, oacc[j][3] * inv1);
    }
}

// ---------------- Launch ----------------
extern "C" void kernel_launch(void* const* d_in, const int* in_sizes, int n_in,
                              void* d_out, int out_size)
{
    const float* Xq  = (const float*)d_in[0];
    const float* Xkv = (const float*)d_in[1];
    const int*   qpos = (const int*)d_in[2];
    const int*   kpos = (const int*)d_in[3];
    const float* Wq  = (const float*)d_in[4];
    const float* Wk  = (const float*)d_in[5];
    const float* Wv  = (const float*)d_in[6];
    const float* Wo  = (const float*)d_in[7];
    float* out = (float*)d_out;

    float *qb, *kb, *vb, *ab;
    cudaGetSymbolAddress((void**)&qb, g_q);
    cudaGetSymbolAddress((void**)&kb, g_k);
    cudaGetSymbolAddress((void**)&vb, g_v);
    cudaGetSymbolAddress((void**)&ab, g_attn);

    const int P_SMEM = 37888;
    const int O_SMEM = 18944;
    cudaFuncSetAttribute(proj_qkv, cudaFuncAttributeMaxDynamicSharedMemorySize, P_SMEM);
    cudaFuncSetAttribute(gemm_o, cudaFuncAttributeMaxDynamicSharedMemorySize, O_SMEM);
    cudaFuncSetAttribute(attn_tc_kernel, cudaFuncAttributeMaxDynamicSharedMemorySize, A_SMEM);

    // Q/K/V projections in one launch (occ-2; bf3 x2t, fp16 x4t)
    proj_qkv<<<dim3(24, 16), 256, P_SMEM>>>(Xq, Wq, qb, Xkv, Wk, kb, Wv, vb);

    // RoPE on q and k, one launch
    rope_fused<<<(QROPE_TOTAL + KROPE_TOTAL + 255) / 256, 256>>>(qb, kb, qpos, kpos);

    // Attention (R9 config, byte-identical)
    attn_tc_kernel<<<dim3(T_/128, NQ, B_), 256, A_SMEM>>>(qb, kb, vb, ab);

    // Output projection (occ-2, x4t)
    gemm_o<<<dim3(16, 16), 256, O_SMEM>>>(ab, Wo, out);
}

// round 13
// speedup vs baseline: 1.0780x; 1.0439x over previous
#include <cuda_runtime.h>
#include <cuda_bf16.h>
#include <cuda_fp16.h>
#include <cstdint>

#define B_  2
#define T_  1024
#define S_  1024
#define NQ  16
#define NKV 4
#define HD  128

// Scratch (allocation-free rule: __device__ globals)
__device__ float g_q[B_*T_*NQ*HD];      // (B,T,NQ,HD)
__device__ float g_k[B_*S_*NKV*HD];     // (B,S,NKV,HD)
__device__ float g_v[B_*S_*NKV*HD];
__device__ float g_attn[B_*T_*NQ*HD];

// ---------------------------------------------------------------------------
// helpers
// ---------------------------------------------------------------------------
__device__ __forceinline__ void mma_bf16(float d[4], const uint32_t a[4], const uint32_t b[2]) {
    asm volatile(
        "mma.sync.aligned.m16n8k16.row.col.f32.bf16.bf16.f32 "
        "{%0,%1,%2,%3}, {%4,%5,%6,%7}, {%8,%9}, {%0,%1,%2,%3};\n"
        : "+f"(d[0]), "+f"(d[1]), "+f"(d[2]), "+f"(d[3])
        : "r"(a[0]), "r"(a[1]), "r"(a[2]), "r"(a[3]), "r"(b[0]), "r"(b[1]));
}
__device__ __forceinline__ void mma_fp16(float d[4], const uint32_t a[4], const uint32_t b[2]) {
    asm volatile(
        "mma.sync.aligned.m16n8k16.row.col.f32.f16.f16.f32 "
        "{%0,%1,%2,%3}, {%4,%5,%6,%7}, {%8,%9}, {%0,%1,%2,%3};\n"
        : "+f"(d[0]), "+f"(d[1]), "+f"(d[2]), "+f"(d[3])
        : "r"(a[0]), "r"(a[1]), "r"(a[2]), "r"(a[3]), "r"(b[0]), "r"(b[1]));
}
__device__ __forceinline__ void ldsm_x4(uint32_t r[4], uint32_t addr) {
    asm volatile("ldmatrix.sync.aligned.m8n8.x4.shared.b16 {%0,%1,%2,%3}, [%4];"
                 : "=r"(r[0]), "=r"(r[1]), "=r"(r[2]), "=r"(r[3]) : "r"(addr));
}
__device__ __forceinline__ void ldsm_x4t(uint32_t r[4], uint32_t addr) {
    asm volatile("ldmatrix.sync.aligned.m8n8.x4.trans.shared.b16 {%0,%1,%2,%3}, [%4];"
                 : "=r"(r[0]), "=r"(r[1]), "=r"(r[2]), "=r"(r[3]) : "r"(addr));
}
__device__ __forceinline__ void ldsm_x2t(uint32_t r[2], uint32_t addr) {
    asm volatile("ldmatrix.sync.aligned.m8n8.x2.trans.shared.b16 {%0,%1}, [%2];"
                 : "=r"(r[0]), "=r"(r[1]) : "r"(addr));
}
__device__ __forceinline__ void bf16_split2(float x, float y, uint32_t& hi, uint32_t& lo) {
    __nv_bfloat16 hx = __float2bfloat16(x);
    __nv_bfloat16 hy = __float2bfloat16(y);
    __nv_bfloat16 lx = __float2bfloat16(x - __bfloat162float(hx));
    __nv_bfloat16 ly = __float2bfloat16(y - __bfloat162float(hy));
    hi = (uint32_t)__bfloat16_as_ushort(hx) | ((uint32_t)__bfloat16_as_ushort(hy) << 16);
    lo = (uint32_t)__bfloat16_as_ushort(lx) | ((uint32_t)__bfloat16_as_ushort(ly) << 16);
}
__device__ __forceinline__ uint32_t fp16_pack2(float x, float y) {
    __half2 h = __floats2half2_rn(x, y);
    return *(uint32_t*)&h;
}

// ---------------------------------------------------------------------------
// GEMM core: C[M,N] = A[M,K] @ B[K,N], CTA 128x128, BK=32, 8 warps 2x4.
// PASSES=3: bf16 hi/lo 3-term split. PASSES=1: 1-pass fp16.
// X4T=1 (x4.trans B gather) ONLY legal in kernels with no PASSES=3 branch
// (shared-kernel regalloc spills bf3 otherwise — R12 lesson).
// ---------------------------------------------------------------------------
template<int PASSES, int X4T>
__device__ __forceinline__ void gemm_core(
    const float* __restrict__ A, const float* __restrict__ Bm, float* __restrict__ C,
    int N, int K, int row0, int col0, char* smraw)
{
    const uint32_t sb = (uint32_t)__cvta_generic_to_shared(smraw);
    constexpr int AHo = 0;
    constexpr int ALo = 10240;
    constexpr int BHo = (PASSES == 3) ? 20480 : 10240;
    constexpr int BLo = 29184;

    const int tid  = threadIdx.x;
    const int lane = tid & 31;
    const int warp = tid >> 5;
    const int grp  = lane >> 2;
    const int qid  = lane & 3;
    const int wm   = (warp >> 2) * 64;
    const int wn   = (warp & 3) * 32;

    float acc[4][4][4];
    #pragma unroll
    for (int i = 0; i < 4; i++)
        #pragma unroll
        for (int j = 0; j < 4; j++)
            #pragma unroll
            for (int c = 0; c < 4; c++) acc[i][j][c] = 0.f;

    float4 aReg[4], bReg[4];
    #pragma unroll
    for (int i = 0; i < 4; i++) {
        int idx = tid + i * 256;
        int ar = idx >> 3, ac = (idx & 7) << 2;
        aReg[i] = *(const float4*)(A + (size_t)(row0 + ar) * K + ac);
        int bk = idx >> 5, bn = (idx & 31) << 2;
        bReg[i] = *(const float4*)(Bm + (size_t)bk * N + col0 + bn);
    }

    for (int k0 = 0; k0 < K; k0 += 32) {
        #pragma unroll
        for (int i = 0; i < 4; i++) {
            int idx = tid + i * 256;
            int ar = idx >> 3, ac = (idx & 7) << 2;
            int aoff = (ar * 40 + ac) << 1;
            int bk = idx >> 5, bn = (idx & 31) << 2;
            int boff = (bk * 136 + bn) << 1;
            if (PASSES == 3) {
                uint32_t h01, l01, h23, l23;
                bf16_split2(aReg[i].x, aReg[i].y, h01, l01);
                bf16_split2(aReg[i].z, aReg[i].w, h23, l23);
                *(uint2*)(smraw + AHo + aoff) = make_uint2(h01, h23);
                *(uint2*)(smraw + ALo + aoff) = make_uint2(l01, l23);
                bf16_split2(bReg[i].x, bReg[i].y, h01, l01);
                bf16_split2(bReg[i].z, bReg[i].w, h23, l23);
                *(uint2*)(smraw + BHo + boff) = make_uint2(h01, h23);
                *(uint2*)(smraw + BLo + boff) = make_uint2(l01, l23);
            } else {
                *(uint2*)(smraw + AHo + aoff) =
                    make_uint2(fp16_pack2(aReg[i].x, aReg[i].y), fp16_pack2(aReg[i].z, aReg[i].w));
                *(uint2*)(smraw + BHo + boff) =
                    make_uint2(fp16_pack2(bReg[i].x, bReg[i].y), fp16_pack2(bReg[i].z, bReg[i].w));
            }
        }
        __syncthreads();

        if (k0 + 32 < K) {
            #pragma unroll
            for (int i = 0; i < 4; i++) {
                int idx = tid + i * 256;
                int ar = idx >> 3, ac = (idx & 7) << 2;
                aReg[i] = *(const float4*)(A + (size_t)(row0 + ar) * K + k0 + 32 + ac);
                int bk = idx >> 5, bn = (idx & 31) << 2;
                bReg[i] = *(const float4*)(Bm + (size_t)(k0 + 32 + bk) * N + col0 + bn);
            }
        }

        #pragma unroll
        for (int kk = 0; kk < 32; kk += 16) {
            uint32_t ah[4][4], al[4][4];
            #pragma unroll
            for (int im = 0; im < 4; im++) {
                int m = wm + im * 16 + (lane & 15);
                uint32_t ab = sb + AHo + ((m * 40 + kk + ((lane >> 4) << 3)) << 1);
                ldsm_x4(ah[im], ab);
                if (PASSES == 3) ldsm_x4(al[im], ab + (ALo - AHo));
            }
            uint32_t bh[4][2], bl[4][2];
            if (X4T) {
                #pragma unroll
                for (int pr = 0; pr < 2; pr++) {
                    int kr = kk + (lane & 15);
                    uint32_t bb = sb + BHo + ((kr * 136 + wn + pr * 16 + ((lane >> 4) << 3)) << 1);
                    uint32_t t4[4];
                    ldsm_x4t(t4, bb);
                    bh[2*pr][0] = t4[0]; bh[2*pr][1] = t4[1];
                    bh[2*pr+1][0] = t4[2]; bh[2*pr+1][1] = t4[3];
                    if (PASSES == 3) {
                        ldsm_x4t(t4, bb + (BLo - BHo));
                        bl[2*pr][0] = t4[0]; bl[2*pr][1] = t4[1];
                        bl[2*pr+1][0] = t4[2]; bl[2*pr+1][1] = t4[3];
                    }
                }
            } else {
                #pragma unroll
                for (int in_ = 0; in_ < 4; in_++) {
                    int kr = kk + (lane & 15);
                    uint32_t bb = sb + BHo + ((kr * 136 + wn + in_ * 8) << 1);
                    ldsm_x2t(bh[in_], bb);
                    if (PASSES == 3) ldsm_x2t(bl[in_], bb + (BLo - BHo));
                }
            }
            #pragma unroll
            for (int im = 0; im < 4; im++)
                #pragma unroll
                for (int in_ = 0; in_ < 4; in_++) {
                    if (PASSES == 3) {
                        mma_bf16(acc[im][in_], ah[im], bh[in_]);
                        mma_bf16(acc[im][in_], ah[im], bl[in_]);
                        mma_bf16(acc[im][in_], al[im], bh[in_]);
                    } else {
                        mma_fp16(acc[im][in_], ah[im], bh[in_]);
                    }
                }
        }
        __syncthreads();
    }

    #pragma unroll
    for (int im = 0; im < 4; im++) {
        int r = row0 + wm + im * 16 + grp;
        #pragma unroll
        for (int in_ = 0; in_ < 4; in_++) {
            int nc = col0 + wn + in_ * 8 + 2 * qid;
            *(float2*)(C + (size_t)r * N + nc)       = make_float2(acc[im][in_][0], acc[im][in_][1]);
            *(float2*)(C + (size_t)(r + 8) * N + nc) = make_float2(acc[im][in_][2], acc[im][in_][3]);
        }
    }
}

// Merged Q/K/V projections, occ-2. ALL branches x2t (R9-exact: keeps kernel-wide
// register demand at the bf3 baseline; x4t here spills — measured R11/R12).
__global__ void __launch_bounds__(256, 2) proj_qkv(
    const float* __restrict__ Xq, const float* __restrict__ Wq, float* __restrict__ Cq,
    const float* __restrict__ Xkv, const float* __restrict__ Wk, float* __restrict__ Ck,
    const float* __restrict__ Wv, float* __restrict__ Cv)
{
    extern __shared__ char smraw[];
    const int bx = blockIdx.x;
    const int row0 = blockIdx.y * 128;
    if (bx < 16)
        gemm_core<3, 0>(Xq, Wq, Cq, 2048, 2048, row0, bx * 128, smraw);
    else if (bx < 20)
        gemm_core<3, 0>(Xkv, Wk, Ck, 512, 2048, row0, (bx - 16) * 128, smraw);
    else
        gemm_core<1, 0>(Xkv, Wv, Cv, 512, 2048, row0, (bx - 20) * 128, smraw);
}

// Output projection (fp16 1-pass, x4t — standalone kernel, regs slack), occ-2.
__global__ void __launch_bounds__(256, 2) gemm_o(
    const float* __restrict__ A, const float* __restrict__ Bm, float* __restrict__ C)
{
    extern __shared__ char smraw[];
    gemm_core<1, 1>(A, Bm, C, 2048, 2048, blockIdx.y * 128, blockIdx.x * 128, smraw);
}

// ---------------- RoPE fused (q then k ranges in one grid) ----------------
#define QROPE_TOTAL (B_*T_*NQ*64)
#define KROPE_TOTAL (B_*S_*NKV*64)

__global__ void rope_fused(float* __restrict__ xq, float* __restrict__ xk,
                           const int* __restrict__ qpos, const int* __restrict__ kpos)
{
    int idx = blockIdx.x * blockDim.x + threadIdx.x;
    float* x;
    const int* pos;
    int Nh;
    if (idx < QROPE_TOTAL) {
        x = xq; pos = qpos; Nh = NQ;
    } else {
        idx -= QROPE_TOTAL;
        if (idx >= KROPE_TOTAL) return;
        x = xk; pos = kpos; Nh = NKV;
    }
    int i   = idx & 63;
    int bln = idx >> 6;
    int bl  = bln / Nh;
    float p    = (float)pos[bl];
    float frac = (float)i * (1.0f / 64.0f);
    float ts   = powf(10000.0f, frac);
    float ang  = p / ts;
    float si = sinf(ang), co = cosf(ang);
    float* base = x + (size_t)bln * HD;
    float x1 = base[i], x2 = base[i + 64];
    base[i]      = x1 * co - x2 * si;
    base[i + 64] = x2 * co + x1 * si;
}

// ---------------------------------------------------------------------------
// Flash attention (R9-verified, byte-identical): occ-2, KV block 32,
// bf16-3x QK^T, fp16 PV with register-built A fragments.
// Smem: QH 0 (34816), QL 34816, KH 69632 (8704), KL 78336, VS 87040 (8704).
// Total 95744 -> 2 CTAs/SM.
// ---------------------------------------------------------------------------
#define A_QH 0
#define A_QL 34816
#define A_KH 69632
#define A_KL 78336
#define A_VS 87040
#define A_SMEM 95744
#define VSH 136

__global__ void __launch_bounds__(256, 2) attn_tc_kernel(
    const float* __restrict__ q, const float* __restrict__ k,
    const float* __restrict__ v, float* __restrict__ o)
{
    extern __shared__ char smraw[];
    const uint32_t sb = (uint32_t)__cvta_generic_to_shared(smraw);

    const int tid  = threadIdx.x;
    const int lane = tid & 31;
    const int warp = tid >> 5;
    const int grp  = lane >> 2;
    const int qid  = lane & 3;
    const int wm   = warp * 16;
    const int t0   = blockIdx.x * 128;
    const int n    = blockIdx.y;
    const int b    = blockIdx.z;
    const int kvh  = n >> 2;

    const float* Qg = q + ((size_t)(b * T_ + t0) * NQ  + n)   * HD;
    const float* Kg = k + ((size_t)(b * S_)      * NKV + kvh) * HD;
    const float* Vg = v + ((size_t)(b * S_)      * NKV + kvh) * HD;

    for (int f = tid; f < 128 * 32; f += 256) {
        int r = f >> 5, c4 = (f & 31) << 2;
        float4 a = *(const float4*)(Qg + (size_t)r * (NQ * HD) + c4);
        uint32_t h01, l01, h23, l23;
        bf16_split2(a.x, a.y, h01, l01);
        bf16_split2(a.z, a.w, h23, l23);
        int off = (r * 136 + c4) << 1;
        *(uint2*)(smraw + A_QH + off) = make_uint2(h01, h23);
        *(uint2*)(smraw + A_QL + off) = make_uint2(l01, l23);
    }

    float m0 = -1e30f, m1 = -1e30f, l0 = 0.f, l1 = 0.f;
    float oacc[16][4];
    #pragma unroll
    for (int j = 0; j < 16; j++)
        #pragma unroll
        for (int c = 0; c < 4; c++) oacc[j][c] = 0.f;

    for (int blk = 0; blk < 32; blk++) {
        __syncthreads();
        {
            const int s0 = blk * 32;
            #pragma unroll
            for (int i = 0; i < 4; i++) {
                int f = tid + i * 256;
                int r = f >> 5, c4 = (f & 31) << 2;
                float4 a = *(const float4*)(Kg + (size_t)(s0 + r) * (NKV * HD) + c4);
                uint32_t h01, l01, h23, l23;
                bf16_split2(a.x, a.y, h01, l01);
                bf16_split2(a.z, a.w, h23, l23);
                int off = (r * 136 + c4) << 1;
                *(uint2*)(smraw + A_KH + off) = make_uint2(h01, h23);
                *(uint2*)(smraw + A_KL + off) = make_uint2(l01, l23);
                float4 vv = *(const float4*)(Vg + (size_t)(s0 + r) * (NKV * HD) + c4);
                *(uint2*)(smraw + A_VS + ((r * VSH + c4) << 1)) =
                    make_uint2(fp16_pack2(vv.x, vv.y), fp16_pack2(vv.z, vv.w));
            }
        }
        __syncthreads();

        float sacc[4][4];
        #pragma unroll
        for (int j = 0; j < 4; j++)
            #pragma unroll
            for (int c = 0; c < 4; c++) sacc[j][c] = 0.f;

        #pragma unroll
        for (int kk = 0; kk < 8; kk++) {
            const int col0h = kk * 16;
            uint32_t ah[4], al[4];
            {
                int m = wm + (lane & 15);
                uint32_t ab = sb + A_QH + ((m * 136 + col0h + ((lane >> 4) << 3)) << 1);
                ldsm_x4(ah, ab);
                ldsm_x4(al, ab + (A_QL - A_QH));
            }
            #pragma unroll
            for (int j2 = 0; j2 < 2; j2++) {
                int row = (j2 * 2 + (lane >> 4)) * 8 + (lane & 7);
                uint32_t bb = sb + A_KH + ((row * 136 + col0h + (lane & 8)) << 1);
                uint32_t bh4[4], bl4[4];
                ldsm_x4(bh4, bb);
                ldsm_x4(bl4, bb + (A_KL - A_KH));
                mma_bf16(sacc[2*j2],   ah, bh4);
                mma_bf16(sacc[2*j2],   ah, bl4);
                mma_bf16(sacc[2*j2],   al, bh4);
                mma_bf16(sacc[2*j2+1], ah, bh4 + 2);
                mma_bf16(sacc[2*j2+1], ah, bl4 + 2);
                mma_bf16(sacc[2*j2+1], al, bh4 + 2);
            }
        }

        float mx0 = -1e30f, mx1 = -1e30f;
        #pragma unroll
        for (int j = 0; j < 4; j++) {
            mx0 = fmaxf(mx0, fmaxf(sacc[j][0], sacc[j][1]));
            mx1 = fmaxf(mx1, fmaxf(sacc[j][2], sacc[j][3]));
        }
        #pragma unroll
        for (int off = 1; off < 4; off <<= 1) {
            mx0 = fmaxf(mx0, __shfl_xor_sync(0xffffffffu, mx0, off));
            mx1 = fmaxf(mx1, __shfl_xor_sync(0xffffffffu, mx1, off));
        }
        float mn0 = fmaxf(m0, mx0), mn1 = fmaxf(m1, mx1);
        float cr0 = __expf(m0 - mn0), cr1 = __expf(m1 - mn1);
        float ps0 = 0.f, ps1 = 0.f;
        uint32_t pk[4][2];
        #pragma unroll
        for (int j = 0; j < 4; j++) {
            float e0 = __expf(sacc[j][0] - mn0);
            float e1 = __expf(sacc[j][1] - mn0);
            float e2 = __expf(sacc[j][2] - mn1);
            float e3 = __expf(sacc[j][3] - mn1);
            ps0 += e0 + e1; ps1 += e2 + e3;
            pk[j][0] = fp16_pack2(e0, e1);
            pk[j][1] = fp16_pack2(e2, e3);
        }
        #pragma unroll
        for (int off = 1; off < 4; off <<= 1) {
            ps0 += __shfl_xor_sync(0xffffffffu, ps0, off);
            ps1 += __shfl_xor_sync(0xffffffffu, ps1, off);
        }
        l0 = l0 * cr0 + ps0; m0 = mn0;
        l1 = l1 * cr1 + ps1; m1 = mn1;
        #pragma unroll
        for (int j = 0; j < 16; j++) {
            oacc[j][0] *= cr0; oacc[j][1] *= cr0;
            oacc[j][2] *= cr1; oacc[j][3] *= cr1;
        }

        #pragma unroll
        for (int kk2 = 0; kk2 < 2; kk2++) {
            uint32_t pa[4] = { pk[2*kk2][0], pk[2*kk2][1], pk[2*kk2+1][0], pk[2*kk2+1][1] };
            #pragma unroll
            for (int j2 = 0; j2 < 8; j2++) {
                int kr  = kk2 * 16 + (lane & 15);
                int col = (j2 * 2 + (lane >> 4)) * 8;
                uint32_t vb4[4];
                ldsm_x4t(vb4, sb + A_VS + ((kr * VSH + col) << 1));
                mma_fp16(oacc[2*j2],     pa, vb4);
                mma_fp16(oacc[2*j2 + 1], pa, vb4 + 2);
            }
        }
    }

    float inv0 = 1.0f / l0, inv1 = 1.0f / l1;
    float* o0 = o + ((size_t)(b * T_ + t0 + wm + grp)     * NQ + n) * HD;
    float* o1 = o + ((size_t)(b * T_ + t0 + wm + grp + 8) * NQ + n) * HD;
    #pragma unroll
    for (int j = 0; j < 16; j++) {
        int col = j * 8 + 2 * qid;
        *(float2*)(o0 + col) = make_float2(oacc[j][0] * inv0, oacc[j][1] * inv0);
        *(float2*)(o1 + col) = make_float2(oacc[j][2] * inv1, oacc[j][3] * inv1);
    }
}

// ---------------- Launch ----------------
extern "C" void kernel_launch(void* const* d_in, const int* in_sizes, int n_in,
                              void* d_out, int out_size)
{
    const float* Xq  = (const float*)d_in[0];
    const float* Xkv = (const float*)d_in[1];
    const int*   qpos = (const int*)d_in[2];
    const int*   kpos = (const int*)d_in[3];
    const float* Wq  = (const float*)d_in[4];
    const float* Wk  = (const float*)d_in[5];
    const float* Wv  = (const float*)d_in[6];
    const float* Wo  = (const float*)d_in[7];
    float* out = (float*)d_out;

    float *qb, *kb, *vb, *ab;
    cudaGetSymbolAddress((void**)&qb, g_q);
    cudaGetSymbolAddress((void**)&kb, g_k);
    cudaGetSymbolAddress((void**)&vb, g_v);
    cudaGetSymbolAddress((void**)&ab, g_attn);

    const int P_SMEM = 37888;
    const int O_SMEM = 18944;
    cudaFuncSetAttribute(proj_qkv, cudaFuncAttributeMaxDynamicSharedMemorySize, P_SMEM);
    cudaFuncSetAttribute(gemm_o, cudaFuncAttributeMaxDynamicSharedMemorySize, O_SMEM);
    cudaFuncSetAttribute(attn_tc_kernel, cudaFuncAttributeMaxDynamicSharedMemorySize, A_SMEM);

    // Q/K/V projections in one launch (occ-2, all-x2t = R9-exact)
    proj_qkv<<<dim3(24, 16), 256, P_SMEM>>>(Xq, Wq, qb, Xkv, Wk, kb, Wv, vb);

    // RoPE on q and k, one launch
    rope_fused<<<(QROPE_TOTAL + KROPE_TOTAL + 255) / 256, 256>>>(qb, kb, qpos, kpos);

    // Attention (R9 config, byte-identical)
    attn_tc_kernel<<<dim3(T_/128, NQ, B_), 256, A_SMEM>>>(qb, kb, vb, ab);

    // Output projection (occ-2, x4t)
    gemm_o<<<dim3(16, 16), 256, O_SMEM>>>(ab, Wo, out);
}